// round 1
// baseline (speedup 1.0000x reference)
#include <cuda_runtime.h>
#include <math.h>

#define BATCH   4
#define SEQ     2048
#define DMODEL  1024
#define DINNER  2048
#define DSTATE  16
#define DTRANK  64
#define DCONV   4
#define MROWS   (BATCH*SEQ)          /* 8192 */
#define XPROJ_N (DTRANK + 2*DSTATE)  /* 96 */

// ---------------- scratch (static device globals; no allocs) ----------------
__device__ float g_xz [MROWS * (2*DINNER)];   // [8192, 4096]  xi | z
__device__ float g_u  [MROWS * DINNER];       // [8192, 2048]
__device__ float g_dbl[MROWS * XPROJ_N];      // [8192, 96]
__device__ float g_dt [MROWS * DINNER];       // [8192, 2048]
__device__ float g_y  [MROWS * DINNER];       // [8192, 2048]

// ---------------- generic NT SGEMM: C[m,n] = sum_k A[m,k] * B[n,k] ----------
// BM=128, BN=128, BK=8, 256 threads, 8x8 microtile.
// Requirements: M % 128 == 0, K % 8 == 0, A-row float4-aligned (lda%4==0, K%4==0).
// N may be arbitrary (guarded B loads / C stores).
// EPI: 0 = plain store, 1 = softplus(acc + bias[n])
template <int EPI>
__global__ void __launch_bounds__(256)
sgemm_nt(const float* __restrict__ A, const float* __restrict__ B,
         float* __restrict__ C, const float* __restrict__ bias,
         int M, int N, int K, int lda, int ldb, int ldc)
{
    __shared__ float As[8][128];
    __shared__ float Bs[8][128];

    const int bm = blockIdx.y * 128;
    const int bn = blockIdx.x * 128;
    const int tid = threadIdx.x;

    const int lr = tid >> 1;          // 0..127 : row within tile
    const int lc = (tid & 1) * 4;     // 0 or 4 : col within 8

    const int tx = tid & 15;          // 0..15
    const int ty = tid >> 4;          // 0..15

    float acc[8][8];
#pragma unroll
    for (int i = 0; i < 8; ++i)
#pragma unroll
        for (int j = 0; j < 8; ++j) acc[i][j] = 0.f;

    for (int k0 = 0; k0 < K; k0 += 8) {
        // load A tile (always in-bounds: M multiple of 128)
        float4 av = *(const float4*)&A[(size_t)(bm + lr) * lda + k0 + lc];
        As[lc + 0][lr] = av.x;
        As[lc + 1][lr] = av.y;
        As[lc + 2][lr] = av.z;
        As[lc + 3][lr] = av.w;

        float4 bv = make_float4(0.f, 0.f, 0.f, 0.f);
        if (bn + lr < N)
            bv = *(const float4*)&B[(size_t)(bn + lr) * ldb + k0 + lc];
        Bs[lc + 0][lr] = bv.x;
        Bs[lc + 1][lr] = bv.y;
        Bs[lc + 2][lr] = bv.z;
        Bs[lc + 3][lr] = bv.w;

        __syncthreads();

#pragma unroll
        for (int k = 0; k < 8; ++k) {
            float a[8], b[8];
#pragma unroll
            for (int i = 0; i < 8; ++i) a[i] = As[k][ty * 8 + i];
#pragma unroll
            for (int j = 0; j < 8; ++j) b[j] = Bs[k][tx * 8 + j];
#pragma unroll
            for (int i = 0; i < 8; ++i)
#pragma unroll
                for (int j = 0; j < 8; ++j)
                    acc[i][j] = fmaf(a[i], b[j], acc[i][j]);
        }
        __syncthreads();
    }

#pragma unroll
    for (int i = 0; i < 8; ++i) {
        const int row = bm + ty * 8 + i;
#pragma unroll
        for (int j = 0; j < 8; ++j) {
            const int col = bn + tx * 8 + j;
            if (col < N) {
                float v = acc[i][j];
                if (EPI == 1) {
                    v += bias[col];
                    // stable softplus = log1p(exp(v))
                    v = (v > 20.f) ? v : log1pf(expf(v));
                }
                C[(size_t)row * ldc + col] = v;
            }
        }
    }
}

// ---------------- depthwise causal conv (K=4) + bias + SiLU ----------------
__global__ void conv_silu_kernel(const float* __restrict__ conv_w,
                                 const float* __restrict__ conv_b)
{
    int idx = blockIdx.x * blockDim.x + threadIdx.x;   // over MROWS*DINNER
    if (idx >= MROWS * DINNER) return;
    const int c = idx & (DINNER - 1);
    const int m = idx >> 11;          // DINNER = 2048 = 2^11
    const int l = m & (SEQ - 1);      // SEQ = 2048

    float acc = conv_b[c];
#pragma unroll
    for (int k = 0; k < DCONV; ++k) {
        const int ll = l + k - (DCONV - 1);
        if (ll >= 0)
            acc = fmaf(g_xz[(size_t)(m + k - (DCONV - 1)) * (2*DINNER) + c],
                       conv_w[c * DCONV + k], acc);
    }
    // silu
    const float sig = 1.f / (1.f + expf(-acc));
    g_u[(size_t)m * DINNER + c] = acc * sig;
}

// ---------------- selective scan over L, fused gate epilogue ----------------
// grid: (DINNER/64, BATCH), block: 64. One thread owns one (b, c) channel.
__global__ void __launch_bounds__(64)
scan_kernel(const float* __restrict__ A_log,
            const float* __restrict__ D_skip)
{
    const int b   = blockIdx.y;
    const int tid = threadIdx.x;
    const int c   = blockIdx.x * 64 + tid;

    float A[DSTATE];
#pragma unroll
    for (int s = 0; s < DSTATE; ++s)
        A[s] = -expf(A_log[c * DSTATE + s]);

    float h[DSTATE];
#pragma unroll
    for (int s = 0; s < DSTATE; ++s) h[s] = 0.f;

    const float dsk = D_skip[c];

    __shared__ float bc[2][32];   // [phase][ B(16) | C(16) ]

    // prefetch B/C for l = 0
    if (tid < 32)
        bc[0][tid] = g_dbl[(size_t)(b * SEQ) * XPROJ_N + DTRANK + tid];
    __syncthreads();

    for (int l = 0; l < SEQ; ++l) {
        const int cur = l & 1;
        if (tid < 32 && l + 1 < SEQ)
            bc[cur ^ 1][tid] = g_dbl[(size_t)(b * SEQ + l + 1) * XPROJ_N + DTRANK + tid];

        const size_t m  = (size_t)(b * SEQ + l);
        const float dt  = g_dt[m * DINNER + c];
        const float ut  = g_u [m * DINNER + c];
        const float zt  = g_xz[m * (2*DINNER) + DINNER + c];
        const float dtu = dt * ut;

        float y = 0.f;
#pragma unroll
        for (int s = 0; s < DSTATE; ++s) {
            const float dA = __expf(dt * A[s]);
            h[s] = fmaf(h[s], dA, dtu * bc[cur][s]);
            y = fmaf(h[s], bc[cur][DSTATE + s], y);
        }

        const float zs = zt / (1.f + __expf(-zt));   // silu(z)
        g_y[m * DINNER + c] = (y + ut * dsk) * zs;

        __syncthreads();
    }
}

// ---------------- launch -----------------------------------------------------
extern "C" void kernel_launch(void* const* d_in, const int* in_sizes, int n_in,
                              void* d_out, int out_size)
{
    const float* x      = (const float*)d_in[0];
    const float* W_in   = (const float*)d_in[1];
    const float* conv_w = (const float*)d_in[2];
    const float* conv_b = (const float*)d_in[3];
    const float* W_xproj= (const float*)d_in[4];
    const float* W_dt   = (const float*)d_in[5];
    const float* b_dt   = (const float*)d_in[6];
    const float* A_log  = (const float*)d_in[7];
    const float* D_skip = (const float*)d_in[8];
    const float* W_out  = (const float*)d_in[9];
    float* out = (float*)d_out;

    float *xz, *u, *dbl, *dt, *y;
    cudaGetSymbolAddress((void**)&xz,  g_xz);
    cudaGetSymbolAddress((void**)&u,   g_u);
    cudaGetSymbolAddress((void**)&dbl, g_dbl);
    cudaGetSymbolAddress((void**)&dt,  g_dt);
    cudaGetSymbolAddress((void**)&y,   g_y);

    dim3 blk(256);

    // G1: xz = x @ W_in^T      [8192, 4096] K=1024
    sgemm_nt<0><<<dim3(4096/128, MROWS/128), blk>>>(
        x, W_in, xz, nullptr, MROWS, 2*DINNER, DMODEL, DMODEL, DMODEL, 2*DINNER);

    // conv + silu -> u
    conv_silu_kernel<<<(MROWS * DINNER + 255) / 256, 256>>>(conv_w, conv_b);

    // G2: dbl = u @ W_xproj^T  [8192, 96] K=2048
    sgemm_nt<0><<<dim3(1, MROWS/128), blk>>>(
        u, W_xproj, dbl, nullptr, MROWS, XPROJ_N, DINNER, DINNER, DINNER, XPROJ_N);

    // G3: dt = softplus(dbl[:, :64] @ W_dt^T + b_dt)   [8192, 2048] K=64
    sgemm_nt<1><<<dim3(DINNER/128, MROWS/128), blk>>>(
        dbl, W_dt, dt, b_dt, MROWS, DINNER, DTRANK, XPROJ_N, DTRANK, DINNER);

    // selective scan + skip + gate -> y
    scan_kernel<<<dim3(DINNER/64, BATCH), 64>>>(A_log, D_skip);

    // G4: out = y @ W_out^T    [8192, 1024] K=2048
    sgemm_nt<0><<<dim3(DMODEL/128, MROWS/128), blk>>>(
        y, W_out, out, nullptr, MROWS, DMODEL, DINNER, DINNER, DINNER, DMODEL);
}